// round 3
// baseline (speedup 1.0000x reference)
#include <cuda_runtime.h>
#include <math.h>

#define MTOT 8192
#define NHALF 4096
#define DDIM 128
#define BM 128
#define BN 128
#define TM 8
#define TN 8
#define LDA 132                 // smem row stride (floats): float4-aligned, spreads STS banks
#define SMEM_BYTES (2 * DDIM * LDA * 4)

__device__ float  g_sq[MTOT];
__device__ float  g_v[DDIM];
__device__ float  g_S;
__device__ float  g_c;          // = log-space scale: 1/(16*bw_base)
__device__ double g_acc;

__global__ void k_init() {
    int t = threadIdx.x;
    if (t < DDIM) g_v[t] = 0.f;
    if (t == 0) { g_S = 0.f; g_acc = 0.0; }
}

// One warp per row: row squared-norm + column sums (for analytic sum(L2))
__global__ void k_rows(const float* __restrict__ src, const float* __restrict__ tgt) {
    __shared__ float cs[DDIM];
    __shared__ float ss;
    int warp = threadIdx.x >> 5, lane = threadIdx.x & 31;
    int row  = blockIdx.x * 8 + warp;
    const float* p = (row < NHALF) ? (src + (size_t)row * DDIM)
                                   : (tgt + (size_t)(row - NHALF) * DDIM);
    float4 x = ((const float4*)p)[lane];
    float s = x.x*x.x + x.y*x.y + x.z*x.z + x.w*x.w;

    if (threadIdx.x < DDIM) cs[threadIdx.x] = 0.f;
    if (threadIdx.x == 0) ss = 0.f;
    __syncthreads();

    atomicAdd(&cs[lane*4+0], x.x);
    atomicAdd(&cs[lane*4+1], x.y);
    atomicAdd(&cs[lane*4+2], x.z);
    atomicAdd(&cs[lane*4+3], x.w);

    #pragma unroll
    for (int o = 16; o; o >>= 1) s += __shfl_xor_sync(0xffffffffu, s, o);
    if (lane == 0) { g_sq[row] = s; atomicAdd(&ss, s); }
    __syncthreads();

    if (threadIdx.x < DDIM) atomicAdd(&g_v[threadIdx.x], cs[threadIdx.x]);
    if (threadIdx.x == 0)   atomicAdd(&g_S, ss);
}

// bandwidth: sum(L2) = 2*M*S - 2*|v|^2 ; bw = sumL2/(M^2-M)/4 ; c = 1/(16*bw)
__global__ void k_bw() {
    __shared__ float part[4];
    int t = threadIdx.x;                 // 128 threads
    float v = g_v[t];
    float vv = v * v;
    #pragma unroll
    for (int o = 16; o; o >>= 1) vv += __shfl_xor_sync(0xffffffffu, vv, o);
    if ((t & 31) == 0) part[t >> 5] = vv;
    __syncthreads();
    if (t == 0) {
        double V = (double)part[0] + part[1] + part[2] + part[3];
        double S = (double)g_S;
        double sumL2 = 2.0 * (double)MTOT * S - 2.0 * V;
        double bw = sumL2 / ((double)MTOT * (double)MTOT - (double)MTOT);
        bw *= 0.25;                       // / KERNEL_MUL^(KERNEL_NUM//2) = /4
        g_c = (float)(1.0 / (16.0 * bw)); // t = exp(-L2*c); kernels = t+t^2+t^4+t^8+t^16
    }
}

extern __shared__ float dsmem[];

__global__ void __launch_bounds__(256)
k_main(const float* __restrict__ src, const float* __restrict__ tgt) {
    int bi = blockIdx.y, bj = blockIdx.x;
    if (bj < bi) return;                  // upper triangle of 64x64 tile grid

    float* As = dsmem;                    // [DDIM][LDA] transposed tile, rows = k
    float* Bs = dsmem + DDIM * LDA;
    __shared__ float sqA[BM], sqB[BN];
    __shared__ float red[8];

    int tid = threadIdx.x;
    int row0 = bi * BM, col0 = bj * BN;   // tile never crosses the 4096 boundary (4096 = 32*128)
    const float* Abase = (row0 < NHALF) ? (src + (size_t)row0 * DDIM)
                                        : (tgt + (size_t)(row0 - NHALF) * DDIM);
    const float* Bbase = (col0 < NHALF) ? (src + (size_t)col0 * DDIM)
                                        : (tgt + (size_t)(col0 - NHALF) * DDIM);

    // Load tiles transposed: As[k][m] = A[m][k]. Lanes walk k (coalesced LDG,
    // STS stride LDA=132 -> 4-way spread, done once per block).
    #pragma unroll 8
    for (int i = 0; i < 64; i++) {
        int idx = tid + i * 256;          // 0..16383
        int k = idx & (DDIM - 1);
        int m = idx >> 7;
        As[k * LDA + m] = Abase[m * DDIM + k];
        Bs[k * LDA + m] = Bbase[m * DDIM + k];
    }
    if (tid < BM)                 sqA[tid]       = g_sq[row0 + tid];
    else if (tid < BM + BN)       sqB[tid - BM]  = g_sq[col0 + tid - BM];
    __syncthreads();

    int ty = tid >> 4, tx = tid & 15;
    int m0 = ty * TM, n0 = tx * TN;

    float acc[TM][TN];
    #pragma unroll
    for (int i = 0; i < TM; i++)
        #pragma unroll
        for (int j = 0; j < TN; j++) acc[i][j] = 0.f;

    #pragma unroll 4
    for (int k = 0; k < DDIM; k++) {
        const float* ar = &As[k * LDA];
        const float* br = &Bs[k * LDA];
        float4 a0 = *(const float4*)(ar + m0);
        float4 a1 = *(const float4*)(ar + m0 + 4);
        float4 b0 = *(const float4*)(br + n0);
        float4 b1 = *(const float4*)(br + n0 + 4);
        float a[TM] = {a0.x,a0.y,a0.z,a0.w,a1.x,a1.y,a1.z,a1.w};
        float b[TN] = {b0.x,b0.y,b0.z,b0.w,b1.x,b1.y,b1.z,b1.w};
        #pragma unroll
        for (int i = 0; i < TM; i++)
            #pragma unroll
            for (int j = 0; j < TN; j++)
                acc[i][j] += a[i] * b[j];
    }

    // Epilogue: 1 exp + repeated squaring for the 5-kernel sum
    float c = g_c;
    float si = (bi < 32) ? 1.f : -1.f;    // 4096/128 = 32 tiles per half
    float sj = (bj < 32) ? 1.f : -1.f;
    float w  = si * sj * ((bi == bj) ? 1.f : 2.f);

    float lsum = 0.f;
    #pragma unroll
    for (int i = 0; i < TM; i++) {
        float sa = sqA[m0 + i];
        #pragma unroll
        for (int j = 0; j < TN; j++) {
            float L2 = sa + sqB[n0 + j] - 2.f * acc[i][j];
            float t  = __expf(-c * L2);
            float t2 = t * t, t4 = t2 * t2, t8 = t4 * t4, t16 = t8 * t8;
            lsum += t + t2 + t4 + t8 + t16;
        }
    }
    lsum *= w;

    #pragma unroll
    for (int o = 16; o; o >>= 1) lsum += __shfl_xor_sync(0xffffffffu, lsum, o);
    if ((tid & 31) == 0) red[tid >> 5] = lsum;
    __syncthreads();
    if (tid == 0) {
        float bsum = 0.f;
        #pragma unroll
        for (int wi = 0; wi < 8; wi++) bsum += red[wi];
        atomicAdd(&g_acc, (double)bsum);   // double accumulator: cross-tile cancellation
    }
}

__global__ void k_final(float* out) {
    out[0] = (float)(g_acc * (1.0 / ((double)NHALF * (double)NHALF)));
}

extern "C" void kernel_launch(void* const* d_in, const int* in_sizes, int n_in,
                              void* d_out, int out_size) {
    const float* src = (const float*)d_in[0];
    const float* tgt = (const float*)d_in[1];
    float* out = (float*)d_out;

    cudaFuncSetAttribute(k_main, cudaFuncAttributeMaxDynamicSharedMemorySize, SMEM_BYTES);

    k_init<<<1, 128>>>();
    k_rows<<<MTOT / 8, 256>>>(src, tgt);
    k_bw<<<1, 128>>>();
    dim3 grid(64, 64);
    k_main<<<grid, 256, SMEM_BYTES>>>(src, tgt);
    k_final<<<1, 1>>>(out);
}